// round 2
// baseline (speedup 1.0000x reference)
#include <cuda_runtime.h>
#include <cuda_fp16.h>
#include <cuda_bf16.h>
#include <cstdint>

// ---------------- problem constants ----------------
#define NS 2
#define CD 256
#define PD 4096            // 64*64
#define EPSF 1e-5f

// ---------------- device scratch (no runtime allocs allowed) ----------------
static __device__ __half        g_dot[(size_t)NS * PD * PD];   // 64 MiB: dot[n][pt][pi]
static __device__ __nv_bfloat16 g_Tn[(size_t)NS * PD * CD];    // normalized T, [n][p][c]
static __device__ __nv_bfloat16 g_In[(size_t)NS * PD * CD];    // normalized I, [n][p][c]
static __device__ float g_meanT[CD];
static __device__ float g_colmin[NS * PD];   // min over pt of raw=(1-dot)/2 per (n,pi); >=0
static __device__ float g_S[NS * PD];        // sum_pt exp(c1*(dot-dmax)) per (n,pi)

// ---------------- small asm helpers (baseline sm_80+ ISA only) ----------------
__device__ __forceinline__ uint32_t smem_to_u32(const void* p) {
    uint32_t a;
    asm("{ .reg .u64 t; cvta.to.shared.u64 t, %1; cvt.u32.u64 %0, t; }" : "=r"(a) : "l"(p));
    return a;
}
#define CP_ASYNC16(dst, src) \
    asm volatile("cp.async.cg.shared.global [%0], [%1], 16;" :: "r"(dst), "l"(src) : "memory")
#define CP_COMMIT() asm volatile("cp.async.commit_group;" ::: "memory")
#define CP_WAIT(N)  asm volatile("cp.async.wait_group %0;" :: "n"(N) : "memory")

#define LDSM_X4(R, addr) \
    asm volatile("ldmatrix.sync.aligned.m8n8.x4.shared.b16 {%0,%1,%2,%3}, [%4];" \
        : "=r"((R)[0]), "=r"((R)[1]), "=r"((R)[2]), "=r"((R)[3]) : "r"(addr))

#define MMA_16816(D, A, B0, B1) \
    asm volatile("mma.sync.aligned.m16n8k16.row.col.f32.bf16.bf16.f32 " \
        "{%0,%1,%2,%3}, {%4,%5,%6,%7}, {%8,%9}, {%0,%1,%2,%3};" \
        : "+f"((D)[0]), "+f"((D)[1]), "+f"((D)[2]), "+f"((D)[3]) \
        : "r"((A)[0]), "r"((A)[1]), "r"((A)[2]), "r"((A)[3]), "r"(B0), "r"(B1))

// FMA-pipe-only exp (avoids MUFU throughput wall). |rel err| < 3e-6 for x in [-80, 1].
__device__ __forceinline__ float fexp(float x) {
    x = fmaxf(x, -80.0f);
    float t = x * 1.4426950408889634f;           // x * log2(e)
    float fn = t + 12582912.0f;                  // round-to-nearest via magic number
    int n = __float_as_int(fn) - 0x4B400000;
    float f = t - (fn - 12582912.0f);            // f in [-0.5, 0.5]
    float p = 1.3333558146e-3f;                  // 2^f Taylor (degree 5)
    p = fmaf(p, f, 9.6181291077e-3f);
    p = fmaf(p, f, 5.5504108664e-2f);
    p = fmaf(p, f, 2.4022650696e-1f);
    p = fmaf(p, f, 6.9314718056e-1f);
    p = fmaf(p, f, 1.0f);
    return __int_as_float(__float_as_int(p) + (n << 23));
}

// ---------------- kernel 0: init accumulators ----------------
__global__ void k_init() {
    int i = blockIdx.x * blockDim.x + threadIdx.x;
    if (i < NS * PD) {
        g_colmin[i] = 3.402823466e38f;  // positive -> int atomicMin is order-correct
        g_S[i] = 0.0f;
    }
}

// ---------------- kernel 1: meanT per channel ----------------
__global__ void k_mean(const float* __restrict__ T) {
    int c = blockIdx.x;
    int tid = threadIdx.x;
    float s = 0.0f;
    for (int n = 0; n < NS; n++) {
        const float* base = T + ((size_t)n * CD + c) * PD;
        for (int p = tid; p < PD; p += 256) s += base[p];
    }
    __shared__ float sh[256];
    sh[tid] = s; __syncthreads();
    for (int o = 128; o > 0; o >>= 1) { if (tid < o) sh[tid] += sh[tid + o]; __syncthreads(); }
    if (tid == 0) g_meanT[c] = sh[0] * (1.0f / (float)(NS * PD));
}

// ---------------- kernel 2: center + L2-normalize + transpose to [n][p][c] bf16 ----------------
#define NORM_PT 32
__global__ void k_norm(const float* __restrict__ X, int which) {
    int n = blockIdx.y;
    int p0 = blockIdx.x * NORM_PT;
    int tid = threadIdx.x;  // 256
    __shared__ float buf[CD][NORM_PT + 1];
    __shared__ float nrm[8][NORM_PT];
    const float* base = X + (size_t)n * CD * PD + p0;
    for (int idx = tid; idx < CD * NORM_PT; idx += 256) {
        int c = idx >> 5, pl = idx & 31;
        buf[c][pl] = base[(size_t)c * PD + pl] - g_meanT[c];
    }
    __syncthreads();
    {
        int pl = tid & 31, j = tid >> 5;
        float s = 0.0f;
        for (int c = j; c < CD; c += 8) { float v = buf[c][pl]; s += v * v; }
        nrm[j][pl] = s;
    }
    __syncthreads();
    if (tid < NORM_PT) {
        float t = 0.0f;
        #pragma unroll
        for (int j = 0; j < 8; j++) t += nrm[j][tid];
        nrm[0][tid] = rsqrtf(t);
    }
    __syncthreads();
    __nv_bfloat16* ob = (which == 0 ? g_Tn : g_In) + ((size_t)n * PD + p0) * CD;
    for (int idx = tid; idx < NORM_PT * CD; idx += 256) {
        int pl = idx >> 8, c = idx & 255;
        ob[(size_t)pl * CD + c] = __float2bfloat16(buf[c][pl] * nrm[0][pl]);
    }
}

// ---------------- kernel 3: bf16 HMMA GEMM -> dot fp16 + column min of raw ----------------
// CTA tile 128x128, K=256 in 4 chunks of 64, 2-stage cp.async pipeline.
// 8 warps: 4 along M (32 rows each) x 2 along N (64 cols each).
#define APITCH 144                 // 72 bf16 per row (64 data + 8 pad), bytes
#define ATILE  (128 * APITCH)      // 18432 B
#define STAGE  (2 * ATILE)         // A+B per stage = 36864 B
#define GEMM_SMEM_BYTES (2 * STAGE)

__device__ __forceinline__ void gemm_load_stage(
    uint32_t sb, int stage, int kc, int tid,
    const __nv_bfloat16* Asrc, const __nv_bfloat16* Bsrc) {
    uint32_t base = sb + stage * STAGE;
    #pragma unroll
    for (int i = 0; i < 4; i++) {
        int id = tid + i * 256;           // 0..1023
        int row = id >> 3, g = id & 7;    // 8 x 16B chunks per 64-col row
        uint32_t dst = base + row * APITCH + g * 16;
        CP_ASYNC16(dst, Asrc + (size_t)row * CD + kc * 64 + g * 8);
        CP_ASYNC16(dst + ATILE, Bsrc + (size_t)row * CD + kc * 64 + g * 8);
    }
}

__global__ void __launch_bounds__(256) k_gemm() {
    extern __shared__ char smem[];
    uint32_t sb = smem_to_u32(smem);
    int tid = threadIdx.x, lane = tid & 31, wid = tid >> 5;
    int n2 = blockIdx.z;
    int pt0 = blockIdx.y * 128;
    int pi0 = blockIdx.x * 128;
    const __nv_bfloat16* Asrc = g_Tn + ((size_t)n2 * PD + pt0) * CD;
    const __nv_bfloat16* Bsrc = g_In + ((size_t)n2 * PD + pi0) * CD;

    float d[2][8][4] = {};

    gemm_load_stage(sb, 0, 0, tid, Asrc, Bsrc); CP_COMMIT();
    gemm_load_stage(sb, 1, 1, tid, Asrc, Bsrc); CP_COMMIT();

    int m0 = (wid & 3) * 32;
    int n0 = (wid >> 2) * 64;
    // ldmatrix lane-address offsets (bytes within a stage)
    uint32_t aOff = (uint32_t)((m0 + (lane & 15)) * APITCH + (lane >> 4) * 16);
    uint32_t bOff = (uint32_t)(ATILE + (n0 + (lane & 7) + (lane >> 4) * 8) * APITCH
                               + ((lane >> 3) & 1) * 16);

    #pragma unroll
    for (int kc = 0; kc < 4; kc++) {
        int s = kc & 1;
        if (kc < 3) { CP_WAIT(1); } else { CP_WAIT(0); }
        __syncthreads();
        uint32_t aB = sb + s * STAGE + aOff;
        uint32_t bB = sb + s * STAGE + bOff;
        #pragma unroll
        for (int kk = 0; kk < 4; kk++) {   // 4 x k16
            uint32_t a[2][4], b[4][4];
            LDSM_X4(a[0], aB + kk * 32);
            LDSM_X4(a[1], aB + 16 * APITCH + kk * 32);
            #pragma unroll
            for (int nb = 0; nb < 4; nb++)
                LDSM_X4(b[nb], bB + nb * 16 * APITCH + kk * 32);
            #pragma unroll
            for (int mi = 0; mi < 2; mi++)
                #pragma unroll
                for (int ni = 0; ni < 8; ni++) {
                    uint32_t* bp = b[ni >> 1];
                    MMA_16816(d[mi][ni], a[mi], bp[(ni & 1) * 2], bp[(ni & 1) * 2 + 1]);
                }
        }
        __syncthreads();
        if (kc < 2) { gemm_load_stage(sb, s, kc + 2, tid, Asrc, Bsrc); CP_COMMIT(); }
    }

    // epilogue: fp16 store + per-column max(dot) -> atomicMin of raw=(1-dot)/2
    int gID = lane >> 2, tig = lane & 3;
    #pragma unroll
    for (int ni = 0; ni < 8; ni++) {
        float mx0 = -2.0f, mx1 = -2.0f;
        int pi = pi0 + n0 + ni * 8 + tig * 2;
        #pragma unroll
        for (int mi = 0; mi < 2; mi++) {
            float* dd = d[mi][ni];
            __half2 h01 = __floats2half2_rn(dd[0], dd[1]);
            __half2 h23 = __floats2half2_rn(dd[2], dd[3]);
            int pt = pt0 + m0 + mi * 16 + gID;
            *(__half2*)(g_dot + ((size_t)n2 * PD + pt) * PD + pi) = h01;
            *(__half2*)(g_dot + ((size_t)n2 * PD + pt + 8) * PD + pi) = h23;
            mx0 = fmaxf(mx0, fmaxf(__low2float(h01), __low2float(h23)));
            mx1 = fmaxf(mx1, fmaxf(__high2float(h01), __high2float(h23)));
        }
        #pragma unroll
        for (int o = 4; o < 32; o <<= 1) {
            mx0 = fmaxf(mx0, __shfl_xor_sync(0xffffffffu, mx0, o));
            mx1 = fmaxf(mx1, __shfl_xor_sync(0xffffffffu, mx1, o));
        }
        if (lane < 4) {
            atomicMin((int*)&g_colmin[(size_t)n2 * PD + pi],
                      __float_as_int(0.5f - 0.5f * mx0));
            atomicMin((int*)&g_colmin[(size_t)n2 * PD + pi + 1],
                      __float_as_int(0.5f - 0.5f * mx1));
        }
    }
}

// ---------------- kernel 4: column sums S[n][pi] = sum_pt exp(c1*(dot-dmax)) ----------------
__global__ void k_sumcols() {
    int n = blockIdx.z;
    int pi = blockIdx.x * 256 + threadIdx.x;
    int pt0 = blockIdx.y * 512;
    float mn = g_colmin[(size_t)n * PD + pi];
    float c1 = 5.0f / (mn + EPSF);
    float dmax = 1.0f - 2.0f * mn;   // column max of dot (exact back-transform)
    const __half* col = g_dot + ((size_t)n * PD + pt0) * PD + pi;
    float s = 0.0f;
    #pragma unroll 8
    for (int r = 0; r < 512; r++)
        s += fexp(c1 * (__half2float(col[(size_t)r * PD]) - dmax));
    atomicAdd(&g_S[(size_t)n * PD + pi], s);
}

// ---------------- kernel 5: final scalar ----------------
// cx_sp is exactly the identity in fp32 (off-diagonal exponents <= -225 underflow),
// so m[pt] = 0.5 * (1 + cx_feat[pt][pt]) and only the dot diagonal is needed.
__global__ void k_final(float* __restrict__ out) {
    __shared__ float sh[256];
    __shared__ float lossn[NS];
    int tid = threadIdx.x;
    for (int n = 0; n < NS; n++) {
        float s = 0.0f;
        for (int p = tid; p < PD; p += 256) {
            float mn = g_colmin[(size_t)n * PD + p];
            float c1 = 5.0f / (mn + EPSF);
            float dmax = 1.0f - 2.0f * mn;
            float dd = __half2float(g_dot[((size_t)n * PD + p) * PD + p]);
            float cxf = fexp(c1 * (dd - dmax)) / g_S[(size_t)n * PD + p];
            s += 0.5f + 0.5f * cxf;
        }
        sh[tid] = s; __syncthreads();
        for (int o = 128; o > 0; o >>= 1) { if (tid < o) sh[tid] += sh[tid + o]; __syncthreads(); }
        if (tid == 0) lossn[n] = -logf(sh[0] * (1.0f / (float)PD));
        __syncthreads();
    }
    if (tid == 0) {
        float acc = 0.0f;
        for (int n = 0; n < NS; n++) acc += lossn[n];
        out[0] = acc * (1.0f / (float)NS);
    }
}

// ---------------- launch ----------------
extern "C" void kernel_launch(void* const* d_in, const int* in_sizes, int n_in,
                              void* d_out, int out_size) {
    const float* I = (const float*)d_in[0];
    const float* T = (const float*)d_in[1];
    float* out = (float*)d_out;

    cudaFuncSetAttribute(k_gemm, cudaFuncAttributeMaxDynamicSharedMemorySize, GEMM_SMEM_BYTES);

    k_init<<<(NS * PD + 255) / 256, 256>>>();
    k_mean<<<CD, 256>>>(T);
    k_norm<<<dim3(PD / NORM_PT, NS), 256>>>(T, 0);   // -> g_Tn
    k_norm<<<dim3(PD / NORM_PT, NS), 256>>>(I, 1);   // -> g_In
    k_gemm<<<dim3(PD / 128, PD / 128, NS), 256, GEMM_SMEM_BYTES>>>();
    k_sumcols<<<dim3(PD / 256, PD / 512, NS), 256>>>();
    k_final<<<1, 256>>>(out);
}

// round 3
// speedup vs baseline: 1.1262x; 1.1262x over previous
#include <cuda_runtime.h>
#include <cuda_fp16.h>
#include <cuda_bf16.h>
#include <cstdint>

// ---------------- problem constants ----------------
#define NS 2
#define CD 256
#define PD 4096            // 64*64
#define EPSF 1e-5f

// ---------------- device scratch (no runtime allocs allowed) ----------------
static __device__ __half        g_dot[(size_t)NS * PD * PD];   // 64 MiB: dot[n][pt][pi]
static __device__ __nv_bfloat16 g_Tn[(size_t)NS * PD * CD];    // normalized T, [n][p][c]
static __device__ __nv_bfloat16 g_In[(size_t)NS * PD * CD];    // normalized I, [n][p][c]
static __device__ float g_meanT[CD];
static __device__ float g_colmin[NS * PD];   // min over pt of raw=(1-dot)/2 per (n,pi); >=0
static __device__ float g_S[NS * PD];        // sum_pt exp(c1*(dot-dmax)) per (n,pi)

// ---------------- asm helpers (baseline sm_80+ ISA only) ----------------
__device__ __forceinline__ uint32_t smem_to_u32(const void* p) {
    uint32_t a;
    asm("{ .reg .u64 t; cvta.to.shared.u64 t, %1; cvt.u32.u64 %0, t; }" : "=r"(a) : "l"(p));
    return a;
}
#define CP_ASYNC16(dst, src) \
    asm volatile("cp.async.cg.shared.global [%0], [%1], 16;" :: "r"(dst), "l"(src) : "memory")
#define CP_COMMIT() asm volatile("cp.async.commit_group;" ::: "memory")
#define CP_WAIT(N)  asm volatile("cp.async.wait_group %0;" :: "n"(N) : "memory")

#define LDSM_X4(R, addr) \
    asm volatile("ldmatrix.sync.aligned.m8n8.x4.shared.b16 {%0,%1,%2,%3}, [%4];" \
        : "=r"((R)[0]), "=r"((R)[1]), "=r"((R)[2]), "=r"((R)[3]) : "r"(addr))

#define MMA_16816(D, A, B0, B1) \
    asm volatile("mma.sync.aligned.m16n8k16.row.col.f32.bf16.bf16.f32 " \
        "{%0,%1,%2,%3}, {%4,%5,%6,%7}, {%8,%9}, {%0,%1,%2,%3};" \
        : "+f"((D)[0]), "+f"((D)[1]), "+f"((D)[2]), "+f"((D)[3]) \
        : "r"((A)[0]), "r"((A)[1]), "r"((A)[2]), "r"((A)[3]), "r"(B0), "r"(B1))

// FMA-pipe-only exp (avoids MUFU throughput wall). |rel err| < 3e-6 for x in [-80, 1].
__device__ __forceinline__ float fexp(float x) {
    x = fmaxf(x, -80.0f);
    float t = x * 1.4426950408889634f;           // x * log2(e)
    float fn = t + 12582912.0f;                  // round-to-nearest via magic number
    int n = __float_as_int(fn) - 0x4B400000;
    float f = t - (fn - 12582912.0f);            // f in [-0.5, 0.5]
    float p = 1.3333558146e-3f;
    p = fmaf(p, f, 9.6181291077e-3f);
    p = fmaf(p, f, 5.5504108664e-2f);
    p = fmaf(p, f, 2.4022650696e-1f);
    p = fmaf(p, f, 6.9314718056e-1f);
    p = fmaf(p, f, 1.0f);
    return __int_as_float(__float_as_int(p) + (n << 23));
}

// ---------------- kernel 1: meanT per channel (+ fused accumulator init) ----------------
__global__ void k_mean(const float* __restrict__ T) {
    int c = blockIdx.x;       // 256
    int tid = threadIdx.x;    // 256
    if (tid < 32) {           // 256 blocks x 32 = 8192 = NS*PD
        int i = c * 32 + tid;
        g_colmin[i] = 3.402823466e38f;
        g_S[i] = 0.0f;
    }
    float s = 0.0f;
    #pragma unroll
    for (int n = 0; n < NS; n++) {
        const float4* b4 = (const float4*)(T + ((size_t)n * CD + c) * PD);
        #pragma unroll
        for (int i = tid; i < PD / 4; i += 256) {
            float4 v = b4[i];
            s += v.x + v.y + v.z + v.w;
        }
    }
    __shared__ float sh[256];
    sh[tid] = s; __syncthreads();
    for (int o = 128; o > 0; o >>= 1) { if (tid < o) sh[tid] += sh[tid + o]; __syncthreads(); }
    if (tid == 0) g_meanT[c] = sh[0] * (1.0f / (float)(NS * PD));
}

// ---------------- kernel 2: center + normalize + transpose, both tensors in one launch ----------------
#define NP 32
#define BPITCH 260   // floats per p-row (256 + 4 pad); 1040 B, 16B-aligned
__global__ void __launch_bounds__(256) k_norm2(const float* __restrict__ I,
                                               const float* __restrict__ T) {
    const float* X = blockIdx.z ? I : T;
    __nv_bfloat16* out = blockIdx.z ? g_In : g_Tn;
    int n = blockIdx.y;
    int p0 = blockIdx.x * NP;
    int tid = threadIdx.x;
    __shared__ float buf[NP][BPITCH];   // [p][c]
    __shared__ float nrm[8][NP];

    const float* base = X + (size_t)n * CD * PD + p0;
    #pragma unroll
    for (int it = 0; it < 8; it++) {
        int idx = it * 256 + tid;       // 2048 = 256 c * 8 float4
        int c = idx >> 3, j = idx & 7;
        float4 v = *(const float4*)(base + (size_t)c * PD + j * 4);
        float mc = g_meanT[c];
        buf[j * 4 + 0][c] = v.x - mc;
        buf[j * 4 + 1][c] = v.y - mc;
        buf[j * 4 + 2][c] = v.z - mc;
        buf[j * 4 + 3][c] = v.w - mc;
    }
    __syncthreads();
    {
        int p = tid >> 3, k = tid & 7;  // 32 p x 8 chunks
        float s = 0.0f;
        #pragma unroll
        for (int m = 0; m < 32; m++) { float v = buf[p][k * 32 + m]; s += v * v; }
        nrm[k][p] = s;
    }
    __syncthreads();
    if (tid < NP) {
        float t = 0.0f;
        #pragma unroll
        for (int k = 0; k < 8; k++) t += nrm[k][tid];
        nrm[0][tid] = rsqrtf(t);
    }
    __syncthreads();
    __nv_bfloat16* ob = out + ((size_t)n * PD + p0) * CD;
    #pragma unroll
    for (int it = 0; it < 4; it++) {
        int idx = it * 256 + tid;       // 1024 = 32 p * 32 uint4
        int p = idx >> 5, q = idx & 31;
        float sc = nrm[0][p];
        float4 v0 = *(float4*)&buf[p][q * 8];
        float4 v1 = *(float4*)&buf[p][q * 8 + 4];
        __nv_bfloat162 b0 = __floats2bfloat162_rn(v0.x * sc, v0.y * sc);
        __nv_bfloat162 b1 = __floats2bfloat162_rn(v0.z * sc, v0.w * sc);
        __nv_bfloat162 b2 = __floats2bfloat162_rn(v1.x * sc, v1.y * sc);
        __nv_bfloat162 b3 = __floats2bfloat162_rn(v1.z * sc, v1.w * sc);
        uint4 u;
        u.x = *(uint32_t*)&b0; u.y = *(uint32_t*)&b1;
        u.z = *(uint32_t*)&b2; u.w = *(uint32_t*)&b3;
        *(uint4*)(ob + (size_t)p * CD + q * 8) = u;
    }
}

// ---------------- kernel 3: bf16 HMMA GEMM 128x256 tile, 3-stage pipeline ----------------
#define BM 128
#define BN 256
#define PITCH 144                 // 64 bf16 (128B) + 16B pad
#define ASZ (BM * PITCH)          // 18432
#define BSZ (BN * PITCH)          // 36864
#define STG (ASZ + BSZ)           // 55296
#define GEMM_SMEM_BYTES (3 * STG) // 165888
#define EPITCH 528                // epilogue fp16 row pitch in bytes (256*2 + 16)

__device__ __forceinline__ void gemm_load_stage(
    uint32_t sb, int stage, int kc, int tid,
    const __nv_bfloat16* Asrc, const __nv_bfloat16* Bsrc) {
    uint32_t base = sb + stage * STG;
    #pragma unroll
    for (int i = 0; i < 2; i++) {              // A: 128 rows x 8 chunks
        int idx = tid + i * 512;
        int row = idx >> 3, g = idx & 7;
        CP_ASYNC16(base + row * PITCH + g * 16, Asrc + (size_t)row * CD + kc * 64 + g * 8);
    }
    #pragma unroll
    for (int i = 0; i < 4; i++) {              // B: 256 rows x 8 chunks
        int idx = tid + i * 512;
        int row = idx >> 3, g = idx & 7;
        CP_ASYNC16(base + ASZ + row * PITCH + g * 16, Bsrc + (size_t)row * CD + kc * 64 + g * 8);
    }
}

__device__ __forceinline__ void gemm_compute_chunk(uint32_t aB, uint32_t bB, float d[2][8][4]) {
    #pragma unroll
    for (int kk = 0; kk < 4; kk++) {
        uint32_t a[2][4], b[4][4];
        LDSM_X4(a[0], aB + kk * 32);
        LDSM_X4(a[1], aB + 16 * PITCH + kk * 32);
        #pragma unroll
        for (int nb = 0; nb < 4; nb++)
            LDSM_X4(b[nb], bB + nb * 16 * PITCH + kk * 32);
        #pragma unroll
        for (int mi = 0; mi < 2; mi++)
            #pragma unroll
            for (int ni = 0; ni < 8; ni++) {
                uint32_t* bp = b[ni >> 1];
                MMA_16816(d[mi][ni], a[mi], bp[(ni & 1) * 2], bp[(ni & 1) * 2 + 1]);
            }
    }
}

__global__ void __launch_bounds__(512, 1) k_gemm() {
    extern __shared__ char smem[];
    uint32_t sb = smem_to_u32(smem);
    int tid = threadIdx.x, lane = tid & 31, wid = tid >> 5;
    int n2 = blockIdx.z;
    int pt0 = blockIdx.y * BM;
    int pi0 = blockIdx.x * BN;
    const __nv_bfloat16* Asrc = g_Tn + ((size_t)n2 * PD + pt0) * CD;
    const __nv_bfloat16* Bsrc = g_In + ((size_t)n2 * PD + pi0) * CD;

    float d[2][8][4] = {};

    gemm_load_stage(sb, 0, 0, tid, Asrc, Bsrc); CP_COMMIT();
    gemm_load_stage(sb, 1, 1, tid, Asrc, Bsrc); CP_COMMIT();
    gemm_load_stage(sb, 2, 2, tid, Asrc, Bsrc); CP_COMMIT();

    int m0 = (wid & 3) * 32;        // 4 M-warps x 32 rows
    int n0 = (wid >> 2) * 64;       // 4 N-warps x 64 cols
    uint32_t aOff = (uint32_t)((m0 + (lane & 15)) * PITCH + (lane >> 4) * 16);
    uint32_t bOff = (uint32_t)(ASZ + (n0 + (lane & 7) + ((lane >> 4) * 8)) * PITCH
                               + ((lane >> 3) & 1) * 16);

    // kc = 0
    CP_WAIT(2); __syncthreads();
    gemm_compute_chunk(sb + 0 * STG + aOff, sb + 0 * STG + bOff, d);
    __syncthreads();
    gemm_load_stage(sb, 0, 3, tid, Asrc, Bsrc); CP_COMMIT();
    // kc = 1
    CP_WAIT(2); __syncthreads();
    gemm_compute_chunk(sb + 1 * STG + aOff, sb + 1 * STG + bOff, d);
    // kc = 2
    CP_WAIT(1); __syncthreads();
    gemm_compute_chunk(sb + 2 * STG + aOff, sb + 2 * STG + bOff, d);
    // kc = 3
    CP_WAIT(0); __syncthreads();
    gemm_compute_chunk(sb + 0 * STG + aOff, sb + 0 * STG + bOff, d);

    // ---- epilogue: stage fp16 tile in smem, colmin via shfl, coalesced uint4 stores ----
    __syncthreads();   // done reading stages; smem reused for fp16 tile
    int gID = lane >> 2, tig = lane & 3;
    #pragma unroll
    for (int ni = 0; ni < 8; ni++) {
        float mx0 = -2.0f, mx1 = -2.0f;
        int col = n0 + ni * 8 + tig * 2;
        #pragma unroll
        for (int mi = 0; mi < 2; mi++) {
            float* dd = d[mi][ni];
            __half2 h01 = __floats2half2_rn(dd[0], dd[1]);
            __half2 h23 = __floats2half2_rn(dd[2], dd[3]);
            int row = m0 + mi * 16 + gID;
            *(__half2*)(smem + row * EPITCH + col * 2) = h01;
            *(__half2*)(smem + (row + 8) * EPITCH + col * 2) = h23;
            mx0 = fmaxf(mx0, fmaxf(__low2float(h01), __low2float(h23)));
            mx1 = fmaxf(mx1, fmaxf(__high2float(h01), __high2float(h23)));
        }
        #pragma unroll
        for (int o = 4; o < 32; o <<= 1) {
            mx0 = fmaxf(mx0, __shfl_xor_sync(0xffffffffu, mx0, o));
            mx1 = fmaxf(mx1, __shfl_xor_sync(0xffffffffu, mx1, o));
        }
        if (lane < 4 && tig == lane) {
            int pi = pi0 + col;
            atomicMin((int*)&g_colmin[(size_t)n2 * PD + pi],
                      __float_as_int(0.5f - 0.5f * mx0));
            atomicMin((int*)&g_colmin[(size_t)n2 * PD + pi + 1],
                      __float_as_int(0.5f - 0.5f * mx1));
        }
    }
    __syncthreads();
    #pragma unroll
    for (int it = 0; it < 8; it++) {
        int idx = it * 512 + tid;          // 4096 = 128 rows x 32 uint4
        int r = idx >> 5, q = idx & 31;
        uint4 v = *(uint4*)(smem + r * EPITCH + q * 16);
        *(uint4*)(g_dot + ((size_t)n2 * PD + pt0 + r) * PD + pi0 + q * 8) = v;
    }
}

// ---------------- kernel 4: column sums S[n][pi] = sum_pt exp(c1*(dot-dmax)) ----------------
__global__ void __launch_bounds__(256) k_sumcols() {
    int n = blockIdx.z;
    int pi = (blockIdx.x * 256 + threadIdx.x) * 2;
    int pt0 = blockIdx.y * 256;
    float2 mn2 = *(float2*)&g_colmin[(size_t)n * PD + pi];
    float c1a = 5.0f / (mn2.x + EPSF), c1b = 5.0f / (mn2.y + EPSF);
    float dma = 1.0f - 2.0f * mn2.x, dmb = 1.0f - 2.0f * mn2.y;
    const __half2* col = (const __half2*)(g_dot + ((size_t)n * PD + pt0) * PD + pi);
    float sa = 0.0f, sb = 0.0f;
    #pragma unroll 8
    for (int r = 0; r < 256; r++) {
        float2 f = __half22float2(col[(size_t)r * (PD / 2)]);
        sa += fexp(c1a * (f.x - dma));
        sb += fexp(c1b * (f.y - dmb));
    }
    atomicAdd(&g_S[(size_t)n * PD + pi], sa);
    atomicAdd(&g_S[(size_t)n * PD + pi + 1], sb);
}

// ---------------- kernel 5: final scalar ----------------
// cx_sp is exactly the identity in fp32 (off-diagonal exponents <= -225 underflow),
// so m[pt] = 0.5 * (1 + cx_feat[pt][pt]) and only the dot diagonal is needed.
__global__ void k_final(float* __restrict__ out) {
    __shared__ float sh[256];
    __shared__ float lossn[NS];
    int tid = threadIdx.x;
    for (int n = 0; n < NS; n++) {
        float s = 0.0f;
        for (int p = tid; p < PD; p += 256) {
            float mn = g_colmin[(size_t)n * PD + p];
            float c1 = 5.0f / (mn + EPSF);
            float dmax = 1.0f - 2.0f * mn;
            float dd = __half2float(g_dot[((size_t)n * PD + p) * PD + p]);
            float cxf = fexp(c1 * (dd - dmax)) / g_S[(size_t)n * PD + p];
            s += 0.5f + 0.5f * cxf;
        }
        sh[tid] = s; __syncthreads();
        for (int o = 128; o > 0; o >>= 1) { if (tid < o) sh[tid] += sh[tid + o]; __syncthreads(); }
        if (tid == 0) lossn[n] = -logf(sh[0] * (1.0f / (float)PD));
        __syncthreads();
    }
    if (tid == 0) {
        float acc = 0.0f;
        for (int n = 0; n < NS; n++) acc += lossn[n];
        out[0] = acc * (1.0f / (float)NS);
    }
}

// ---------------- launch ----------------
extern "C" void kernel_launch(void* const* d_in, const int* in_sizes, int n_in,
                              void* d_out, int out_size) {
    const float* I = (const float*)d_in[0];
    const float* T = (const float*)d_in[1];
    float* out = (float*)d_out;

    cudaFuncSetAttribute(k_gemm, cudaFuncAttributeMaxDynamicSharedMemorySize, GEMM_SMEM_BYTES);

    k_mean<<<CD, 256>>>(T);
    k_norm2<<<dim3(PD / NP, NS, 2), 256>>>(I, T);
    k_gemm<<<dim3(PD / BN, PD / BM, NS), 512, GEMM_SMEM_BYTES>>>();
    k_sumcols<<<dim3(PD / 512, PD / 256, NS), 256>>>();
    k_final<<<1, 256>>>(out);
}

// round 4
// speedup vs baseline: 1.2713x; 1.1288x over previous
#include <cuda_runtime.h>
#include <cuda_fp16.h>
#include <cuda_bf16.h>
#include <cstdint>

// ---------------- problem constants ----------------
#define NS 2
#define CD 256
#define PD 4096            // 64*64
#define EPSF 1e-5f
#define LOG2E 1.4426950408889634f

// ---------------- device scratch (no runtime allocs allowed) ----------------
static __device__ __half   g_dot[(size_t)NS * PD * PD];   // 64 MiB: dot[n][pt][pi]
static __device__ uint8_t  g_Tn[(size_t)NS * PD * CD];    // normalized T, fp8 e4m3 x16, [n][p][c]
static __device__ uint8_t  g_In[(size_t)NS * PD * CD];    // normalized I, fp8 e4m3 x16, [n][p][c]
static __device__ float g_meanT[CD];
static __device__ float g_colmin[NS * PD];   // min over pt of raw=(1-dot)/2 per (n,pi); >=0
static __device__ float g_S[NS * PD];        // sum_pt exp(c1*(dot-dmax)) per (n,pi)

// ---------------- asm helpers (baseline sm_80/sm_89 ISA only) ----------------
__device__ __forceinline__ uint32_t smem_to_u32(const void* p) {
    uint32_t a;
    asm("{ .reg .u64 t; cvta.to.shared.u64 t, %1; cvt.u32.u64 %0, t; }" : "=r"(a) : "l"(p));
    return a;
}
#define CP_ASYNC16(dst, src) \
    asm volatile("cp.async.cg.shared.global [%0], [%1], 16;" :: "r"(dst), "l"(src) : "memory")
#define CP_COMMIT() asm volatile("cp.async.commit_group;" ::: "memory")
#define CP_WAIT(N)  asm volatile("cp.async.wait_group %0;" :: "n"(N) : "memory")

#define LDSM_X4(R, addr) \
    asm volatile("ldmatrix.sync.aligned.m8n8.x4.shared.b16 {%0,%1,%2,%3}, [%4];" \
        : "=r"((R)[0]), "=r"((R)[1]), "=r"((R)[2]), "=r"((R)[3]) : "r"(addr))

// fp8 e4m3 MMA: m16n8k32, A row-major (K-major), B col-major (K-major), f32 accum
#define MMA_FP8(D, A, B0, B1) \
    asm volatile("mma.sync.aligned.m16n8k32.row.col.f32.e4m3.e4m3.f32 " \
        "{%0,%1,%2,%3}, {%4,%5,%6,%7}, {%8,%9}, {%0,%1,%2,%3};" \
        : "+f"((D)[0]), "+f"((D)[1]), "+f"((D)[2]), "+f"((D)[3]) \
        : "r"((A)[0]), "r"((A)[1]), "r"((A)[2]), "r"((A)[3]), "r"(B0), "r"(B1))

// pack two floats -> e4m3x2 (lo = first elem, hi = second elem)
__device__ __forceinline__ uint16_t pack_e4m3(float lo, float hi) {
    uint16_t r;
    asm("cvt.rn.satfinite.e4m3x2.f32 %0, %1, %2;" : "=h"(r) : "f"(hi), "f"(lo));
    return r;
}
__device__ __forceinline__ float ex2(float x) {
    float r;
    asm("ex2.approx.ftz.f32 %0, %1;" : "=f"(r) : "f"(x));
    return r;
}
// FMA-pipe exp for the tiny final kernel
__device__ __forceinline__ float fexp(float x) {
    return ex2(fmaxf(x, -120.0f) * LOG2E);
}

// ---------------- kernel 1: meanT per channel (+ fused accumulator init) ----------------
__global__ void k_mean(const float* __restrict__ T) {
    int c = blockIdx.x;       // 256
    int tid = threadIdx.x;    // 256
    if (tid < 32) {           // 256 blocks x 32 = 8192 = NS*PD
        int i = c * 32 + tid;
        g_colmin[i] = 3.402823466e38f;
        g_S[i] = 0.0f;
    }
    float s = 0.0f;
    #pragma unroll
    for (int n = 0; n < NS; n++) {
        const float4* b4 = (const float4*)(T + ((size_t)n * CD + c) * PD);
        #pragma unroll
        for (int i = tid; i < PD / 4; i += 256) {
            float4 v = b4[i];
            s += v.x + v.y + v.z + v.w;
        }
    }
    __shared__ float sh[256];
    sh[tid] = s; __syncthreads();
    for (int o = 128; o > 0; o >>= 1) { if (tid < o) sh[tid] += sh[tid + o]; __syncthreads(); }
    if (tid == 0) g_meanT[c] = sh[0] * (1.0f / (float)(NS * PD));
}

// ---------------- kernel 2: center + normalize(+x16) + transpose -> fp8 ----------------
#define NP 32
#define BPITCH 260   // floats per p-row (256 + 4 pad)
__global__ void __launch_bounds__(256) k_norm2(const float* __restrict__ I,
                                               const float* __restrict__ T) {
    const float* X = blockIdx.z ? I : T;
    uint8_t* out = blockIdx.z ? g_In : g_Tn;
    int n = blockIdx.y;
    int p0 = blockIdx.x * NP;
    int tid = threadIdx.x;
    __shared__ float buf[NP][BPITCH];   // [p][c]
    __shared__ float nrm[8][NP];

    const float* base = X + (size_t)n * CD * PD + p0;
    #pragma unroll
    for (int it = 0; it < 8; it++) {
        int idx = it * 256 + tid;       // 2048 = 256 c * 8 float4
        int c = idx >> 3, j = idx & 7;
        float4 v = *(const float4*)(base + (size_t)c * PD + j * 4);
        float mc = g_meanT[c];
        buf[j * 4 + 0][c] = v.x - mc;
        buf[j * 4 + 1][c] = v.y - mc;
        buf[j * 4 + 2][c] = v.z - mc;
        buf[j * 4 + 3][c] = v.w - mc;
    }
    __syncthreads();
    {
        int p = tid >> 3, k = tid & 7;  // 32 p x 8 chunks
        float s = 0.0f;
        #pragma unroll
        for (int m = 0; m < 32; m++) { float v = buf[p][k * 32 + m]; s += v * v; }
        nrm[k][p] = s;
    }
    __syncthreads();
    if (tid < NP) {
        float t = 0.0f;
        #pragma unroll
        for (int k = 0; k < 8; k++) t += nrm[k][tid];
        nrm[0][tid] = rsqrtf(t) * 16.0f;   // x16 scale: e4m3 values ~O(1)
    }
    __syncthreads();
    uint8_t* ob = out + ((size_t)n * PD + p0) * CD;
    #pragma unroll
    for (int it = 0; it < 4; it++) {
        int idx = it * 256 + tid;       // 1024 = 32 p * 32 8-byte groups
        int p = idx >> 5, q = idx & 31;
        float sc = nrm[0][p];
        float4 v0 = *(float4*)&buf[p][q * 8];
        float4 v1 = *(float4*)&buf[p][q * 8 + 4];
        uint16_t h0 = pack_e4m3(v0.x * sc, v0.y * sc);
        uint16_t h1 = pack_e4m3(v0.z * sc, v0.w * sc);
        uint16_t h2 = pack_e4m3(v1.x * sc, v1.y * sc);
        uint16_t h3 = pack_e4m3(v1.z * sc, v1.w * sc);
        uint2 u;
        u.x = (uint32_t)h0 | ((uint32_t)h1 << 16);
        u.y = (uint32_t)h2 | ((uint32_t)h3 << 16);
        *(uint2*)(ob + (size_t)p * CD + q * 8) = u;
    }
}

// ---------------- kernel 3: fp8 MMA GEMM 128x256 tile, 2-stage (K=2x128) ----------------
#define BM 128
#define BN 256
#define PITCH 144                 // 128 fp8 bytes + 16B pad
#define ASZ (BM * PITCH)          // 18432
#define BSZ (BN * PITCH)          // 36864
#define STG (ASZ + BSZ)           // 55296
#define GEMM_SMEM_BYTES (2 * STG) // 110592
#define EPITCH 528                // epilogue fp16 row pitch (256*2 + 16)

__device__ __forceinline__ void gemm_load_stage(
    uint32_t sb, int stage, int kc, int tid,
    const uint8_t* Asrc, const uint8_t* Bsrc) {
    uint32_t base = sb + stage * STG;
    {                                           // A: 128 rows x 8 chunks = 1024
        int idx = tid + (tid >> 31), row = idx >> 3, g = idx & 7;   // 512 threads -> 2 iters
        #pragma unroll
        for (int i = 0; i < 2; i++) {
            int id = tid + i * 512;
            row = id >> 3; g = id & 7;
            CP_ASYNC16(base + row * PITCH + g * 16, Asrc + (size_t)row * CD + kc * 128 + g * 16);
        }
    }
    #pragma unroll
    for (int i = 0; i < 4; i++) {               // B: 256 rows x 8 chunks = 2048
        int id = tid + i * 512;
        int row = id >> 3, g = id & 7;
        CP_ASYNC16(base + ASZ + row * PITCH + g * 16, Bsrc + (size_t)row * CD + kc * 128 + g * 16);
    }
}

__device__ __forceinline__ void gemm_compute_chunk(uint32_t aB, uint32_t bB, float d[2][8][4]) {
    #pragma unroll
    for (int kk = 0; kk < 4; kk++) {   // 4 x k32 (32 bytes each)
        uint32_t a[2][4], b[4][4];
        LDSM_X4(a[0], aB + kk * 32);
        LDSM_X4(a[1], aB + 16 * PITCH + kk * 32);
        #pragma unroll
        for (int nb = 0; nb < 4; nb++)
            LDSM_X4(b[nb], bB + nb * 16 * PITCH + kk * 32);
        #pragma unroll
        for (int mi = 0; mi < 2; mi++)
            #pragma unroll
            for (int ni = 0; ni < 8; ni++) {
                uint32_t* bp = b[ni >> 1];
                MMA_FP8(d[mi][ni], a[mi], bp[(ni & 1) * 2], bp[(ni & 1) * 2 + 1]);
            }
    }
}

__global__ void __launch_bounds__(512, 1) k_gemm() {
    extern __shared__ char smem[];
    uint32_t sb = smem_to_u32(smem);
    int tid = threadIdx.x, lane = tid & 31, wid = tid >> 5;
    int n2 = blockIdx.z;
    int pt0 = blockIdx.y * BM;
    int pi0 = blockIdx.x * BN;
    const uint8_t* Asrc = g_Tn + ((size_t)n2 * PD + pt0) * CD;
    const uint8_t* Bsrc = g_In + ((size_t)n2 * PD + pi0) * CD;

    float d[2][8][4] = {};

    gemm_load_stage(sb, 0, 0, tid, Asrc, Bsrc); CP_COMMIT();
    gemm_load_stage(sb, 1, 1, tid, Asrc, Bsrc); CP_COMMIT();

    int m0 = (wid & 3) * 32;        // 4 M-warps x 32 rows
    int n0 = (wid >> 2) * 64;       // 4 N-warps x 64 cols
    uint32_t aOff = (uint32_t)((m0 + (lane & 15)) * PITCH + (lane >> 4) * 16);
    uint32_t bOff = (uint32_t)(ASZ + (n0 + (lane & 7) + ((lane >> 4) * 8)) * PITCH
                               + ((lane >> 3) & 1) * 16);

    CP_WAIT(1); __syncthreads();
    gemm_compute_chunk(sb + aOff, sb + bOff, d);
    CP_WAIT(0); __syncthreads();
    gemm_compute_chunk(sb + STG + aOff, sb + STG + bOff, d);

    // ---- epilogue: rescale 1/256, stage fp16 tile in smem, colmin via shfl ----
    __syncthreads();   // done reading stages; smem reused for fp16 tile
    const float RS = 1.0f / 256.0f;   // undo the x16*x16 feature scaling
    int gID = lane >> 2, tig = lane & 3;
    #pragma unroll
    for (int ni = 0; ni < 8; ni++) {
        float mx0 = -2.0f, mx1 = -2.0f;
        int col = n0 + ni * 8 + tig * 2;
        #pragma unroll
        for (int mi = 0; mi < 2; mi++) {
            float* dd = d[mi][ni];
            __half2 h01 = __floats2half2_rn(dd[0] * RS, dd[1] * RS);
            __half2 h23 = __floats2half2_rn(dd[2] * RS, dd[3] * RS);
            int row = m0 + mi * 16 + gID;
            *(__half2*)(smem + row * EPITCH + col * 2) = h01;
            *(__half2*)(smem + (row + 8) * EPITCH + col * 2) = h23;
            mx0 = fmaxf(mx0, fmaxf(__low2float(h01), __low2float(h23)));
            mx1 = fmaxf(mx1, fmaxf(__high2float(h01), __high2float(h23)));
        }
        #pragma unroll
        for (int o = 4; o < 32; o <<= 1) {
            mx0 = fmaxf(mx0, __shfl_xor_sync(0xffffffffu, mx0, o));
            mx1 = fmaxf(mx1, __shfl_xor_sync(0xffffffffu, mx1, o));
        }
        if (lane < 4 && tig == lane) {
            int pi = pi0 + col;
            atomicMin((int*)&g_colmin[(size_t)n2 * PD + pi],
                      __float_as_int(0.5f - 0.5f * mx0));
            atomicMin((int*)&g_colmin[(size_t)n2 * PD + pi + 1],
                      __float_as_int(0.5f - 0.5f * mx1));
        }
    }
    __syncthreads();
    #pragma unroll
    for (int it = 0; it < 8; it++) {
        int idx = it * 512 + tid;          // 4096 = 128 rows x 32 uint4
        int r = idx >> 5, q = idx & 31;
        uint4 v = *(uint4*)(smem + r * EPITCH + q * 16);
        *(uint4*)(g_dot + ((size_t)n2 * PD + pt0 + r) * PD + pi0 + q * 8) = v;
    }
}

// ---------------- kernel 4: column sums S[n][pi] = sum_pt exp(c1*(dot-dmax)) ----------------
// MUFU ex2 path: exp(c1*(d-dmax)) = ex2(c2*d - c2*dmax), c2 = c1*log2(e)
__global__ void __launch_bounds__(256) k_sumcols() {
    int n = blockIdx.z;
    int pi = (blockIdx.x * 256 + threadIdx.x) * 2;
    int pt0 = blockIdx.y * 64;
    float2 mn2 = *(float2*)&g_colmin[(size_t)n * PD + pi];
    float c2a = (5.0f * LOG2E) / (mn2.x + EPSF), c2b = (5.0f * LOG2E) / (mn2.y + EPSF);
    float ba = -c2a * (1.0f - 2.0f * mn2.x);   // -c2*dmax
    float bb = -c2b * (1.0f - 2.0f * mn2.y);
    const __half2* col = (const __half2*)(g_dot + ((size_t)n * PD + pt0) * PD + pi);
    float sa = 0.0f, sb = 0.0f;
    #pragma unroll 16
    for (int r = 0; r < 64; r++) {
        float2 f = __half22float2(col[(size_t)r * (PD / 2)]);
        sa += ex2(fmaf(f.x, c2a, ba));
        sb += ex2(fmaf(f.y, c2b, bb));
    }
    atomicAdd(&g_S[(size_t)n * PD + pi], sa);
    atomicAdd(&g_S[(size_t)n * PD + pi + 1], sb);
}

// ---------------- kernel 5: final scalar ----------------
// cx_sp is exactly the identity in fp32 (off-diagonal exponents <= -225 underflow),
// so m[pt] = 0.5 * (1 + cx_feat[pt][pt]) and only the dot diagonal is needed.
__global__ void k_final(float* __restrict__ out) {
    __shared__ float sh[256];
    __shared__ float lossn[NS];
    int tid = threadIdx.x;
    for (int n = 0; n < NS; n++) {
        float s = 0.0f;
        for (int p = tid; p < PD; p += 256) {
            float mn = g_colmin[(size_t)n * PD + p];
            float c1 = 5.0f / (mn + EPSF);
            float dmax = 1.0f - 2.0f * mn;
            float dd = __half2float(g_dot[((size_t)n * PD + p) * PD + p]);
            float cxf = fexp(c1 * (dd - dmax)) / g_S[(size_t)n * PD + p];
            s += 0.5f + 0.5f * cxf;
        }
        sh[tid] = s; __syncthreads();
        for (int o = 128; o > 0; o >>= 1) { if (tid < o) sh[tid] += sh[tid + o]; __syncthreads(); }
        if (tid == 0) lossn[n] = -logf(sh[0] * (1.0f / (float)PD));
        __syncthreads();
    }
    if (tid == 0) {
        float acc = 0.0f;
        for (int n = 0; n < NS; n++) acc += lossn[n];
        out[0] = acc * (1.0f / (float)NS);
    }
}

// ---------------- launch ----------------
extern "C" void kernel_launch(void* const* d_in, const int* in_sizes, int n_in,
                              void* d_out, int out_size) {
    const float* I = (const float*)d_in[0];
    const float* T = (const float*)d_in[1];
    float* out = (float*)d_out;

    cudaFuncSetAttribute(k_gemm, cudaFuncAttributeMaxDynamicSharedMemorySize, GEMM_SMEM_BYTES);

    k_mean<<<CD, 256>>>(T);
    k_norm2<<<dim3(PD / NP, NS, 2), 256>>>(I, T);
    k_gemm<<<dim3(PD / BN, PD / BM, NS), 512, GEMM_SMEM_BYTES>>>();
    k_sumcols<<<dim3(PD / 512, PD / 64, NS), 256>>>();
    k_final<<<1, 256>>>(out);
}